// round 1
// baseline (speedup 1.0000x reference)
#include <cuda_runtime.h>
#include <math.h>

// Problem constants
#define NN   4096
#define EE   131072
#define ETOT (EE + NN)          // edges + self loops for GAT layers
#define NEG_SLOPE 0.2f

// ---------------- scratch (device globals; no allocation) ----------------
__device__ float              g_z[NN * 3];     // per-node features z (stride 3, or stride 1 for layer 3)
__device__ float              g_zs[NN];        // z @ a_s
__device__ float              g_zd[NN];        // z @ a_d
__device__ unsigned int       g_mkey[NN];      // encoded segment max
__device__ float              g_ssum[NN];      // segment sum of w
__device__ float              g_acc[NN * 3];   // segment sum of w*z (layers 1,2)
__device__ float              g_acc3[NN];      // segment sum of w*z (layer 3)
__device__ float              g_xf[NN];        // softmax output
__device__ unsigned long long g_ckey[NN];      // chain argmax key per source node
__device__ int                g_next[NN];      // fixed step map
__device__ int                g_start;
__device__ float              g_p12;

// float <-> totally-ordered uint encoding (preserves float ordering incl. negatives)
__device__ __forceinline__ unsigned int fenc(float f) {
    unsigned int u = __float_as_uint(f);
    return (u & 0x80000000u) ? ~u : (u | 0x80000000u);
}
__device__ __forceinline__ float fdec(unsigned int u) {
    u = (u & 0x80000000u) ? (u & 0x7FFFFFFFu) : ~u;
    return __uint_as_float(u);
}
__device__ __forceinline__ float leaky(float x) { return x >= 0.0f ? x : NEG_SLOPE * x; }

// ---------------- kernels ----------------

// Layer-1 prep: z1 = x * W1^T, zs/zd dots, init all accumulators
__global__ void k_node0(const float* __restrict__ x, const float* __restrict__ W1,
                        const float* __restrict__ as1, const float* __restrict__ ad1) {
    int i = blockIdx.x * blockDim.x + threadIdx.x;
    if (i >= NN) return;
    float xi = x[i];
    float zs = 0.f, zd = 0.f;
#pragma unroll
    for (int k = 0; k < 3; k++) {
        float z = xi * W1[k];
        g_z[i * 3 + k] = z;
        zs += z * as1[k];
        zd += z * ad1[k];
        g_acc[i * 3 + k] = 0.f;
    }
    g_zs[i] = zs; g_zd[i] = zd;
    g_mkey[i] = 0u; g_ssum[i] = 0.f;
    g_ckey[i] = 0ull;
}

// Edge pass A: segment max of leaky(zs[src]+zd[dst]) over dst
__global__ void k_edge_max(const int* __restrict__ ei) {
    int t = blockIdx.x * blockDim.x + threadIdx.x;
    if (t >= ETOT) return;
    int s, d;
    if (t < EE) { s = ei[t]; d = ei[EE + t]; } else { s = t - EE; d = s; }
    float e = leaky(g_zs[s] + g_zd[d]);
    atomicMax(&g_mkey[d], fenc(e));
}

// Edge pass B (HID=3): w = exp(e - m[dst]); accumulate sums
__global__ void k_edge_acc3(const int* __restrict__ ei) {
    int t = blockIdx.x * blockDim.x + threadIdx.x;
    if (t >= ETOT) return;
    int s, d;
    if (t < EE) { s = ei[t]; d = ei[EE + t]; } else { s = t - EE; d = s; }
    float e = leaky(g_zs[s] + g_zd[d]);
    float w = expf(e - fdec(g_mkey[d]));
    atomicAdd(&g_ssum[d], w);
#pragma unroll
    for (int k = 0; k < 3; k++)
        atomicAdd(&g_acc[d * 3 + k], w * g_z[s * 3 + k]);
}

// Edge pass B (HID=1, layer 3): accumulate into g_acc3
__global__ void k_edge_acc1(const int* __restrict__ ei) {
    int t = blockIdx.x * blockDim.x + threadIdx.x;
    if (t >= ETOT) return;
    int s, d;
    if (t < EE) { s = ei[t]; d = ei[EE + t]; } else { s = t - EE; d = s; }
    float e = leaky(g_zs[s] + g_zd[d]);
    float w = expf(e - fdec(g_mkey[d]));
    atomicAdd(&g_ssum[d], w);
    atomicAdd(&g_acc3[d], w * g_z[s]);
}

// Finalize layer 1 -> prep layer 2
__global__ void k_node12(const float* __restrict__ W2, const float* __restrict__ as2,
                         const float* __restrict__ ad2, const float* __restrict__ b1) {
    int i = blockIdx.x * blockDim.x + threadIdx.x;
    if (i >= NN) return;
    float inv = 1.0f / (g_ssum[i] + 1e-16f);
    float h[3];
#pragma unroll
    for (int k = 0; k < 3; k++) {
        float v = g_acc[i * 3 + k] * inv + b1[k];
        h[k] = v > 0.f ? v : 0.f;
    }
    float zs = 0.f, zd = 0.f;
#pragma unroll
    for (int k = 0; k < 3; k++) {
        float z = 0.f;
#pragma unroll
        for (int c = 0; c < 3; c++) z += h[c] * W2[k * 3 + c];
        g_z[i * 3 + k] = z;
        zs += z * as2[k];
        zd += z * ad2[k];
        g_acc[i * 3 + k] = 0.f;
    }
    g_zs[i] = zs; g_zd[i] = zd;
    g_mkey[i] = 0u; g_ssum[i] = 0.f;
}

// Finalize layer 2 -> prep layer 3 (HID=1)
__global__ void k_node23(const float* __restrict__ W3, const float* __restrict__ as3,
                         const float* __restrict__ ad3, const float* __restrict__ b2) {
    int i = blockIdx.x * blockDim.x + threadIdx.x;
    if (i >= NN) return;
    float inv = 1.0f / (g_ssum[i] + 1e-16f);
    float z = 0.f;
#pragma unroll
    for (int c = 0; c < 3; c++) {
        float v = g_acc[i * 3 + c] * inv + b2[c];
        float h = v > 0.f ? v : 0.f;
        z += h * W3[c];
    }
    g_z[i]  = z;           // stride-1 reuse for layer 3
    g_zs[i] = z * as3[0];
    g_zd[i] = z * ad3[0];
    g_acc3[i] = 0.f;
    g_mkey[i] = 0u; g_ssum[i] = 0.f;
}

// Softmax over nodes + argmax(start) + p12, single block of 1024 threads (4 elems each)
__global__ void k_softmax(const float* __restrict__ b3, const float* __restrict__ phi1,
                          const float* __restrict__ phi2, float* __restrict__ out) {
    __shared__ float sred[1024];
    __shared__ unsigned long long skey[1024];
    int tid = threadIdx.x;
    float b = b3[0];
    float v[4];
    float lmax = -INFINITY;
#pragma unroll
    for (int r = 0; r < 4; r++) {
        int i = tid + r * 1024;
        float o = g_acc3[i] / (g_ssum[i] + 1e-16f) + b;
        v[r] = o;
        lmax = fmaxf(lmax, o);
    }
    sred[tid] = lmax; __syncthreads();
    for (int s = 512; s > 0; s >>= 1) { if (tid < s) sred[tid] = fmaxf(sred[tid], sred[tid + s]); __syncthreads(); }
    float m = sred[0]; __syncthreads();

    float lsum = 0.f;
#pragma unroll
    for (int r = 0; r < 4; r++) { v[r] = expf(v[r] - m); lsum += v[r]; }
    sred[tid] = lsum; __syncthreads();
    for (int s = 512; s > 0; s >>= 1) { if (tid < s) sred[tid] += sred[tid + s]; __syncthreads(); }
    float sum = sred[0]; __syncthreads();

    unsigned long long lkey = 0ull;
#pragma unroll
    for (int r = 0; r < 4; r++) {
        int i = tid + r * 1024;
        float xo = v[r] / sum;
        out[i] = xo;
        g_xf[i] = xo;
        unsigned long long k =
            ((unsigned long long)fenc(xo) << 32) | (unsigned long long)(0xFFFFFFFFu - (unsigned)i);
        if (k > lkey) lkey = k;
    }
    skey[tid] = lkey; __syncthreads();
    for (int s = 512; s > 0; s >>= 1) { if (tid < s) skey[tid] = max(skey[tid], skey[tid + s]); __syncthreads(); }

    // p12 = dot(phi1, phi2) over 128
    if (tid < 128) sred[tid] = phi1[tid] * phi2[tid];
    __syncthreads();
    for (int s = 64; s > 0; s >>= 1) { if (tid < s) sred[tid] += sred[tid + s]; __syncthreads(); }
    if (tid == 0) {
        g_p12 = sred[0];
        g_start = (int)(0xFFFFFFFFu - (unsigned)(skey[0] & 0xFFFFFFFFull));
    }
}

// Per-edge chain score; lexicographic (score, min original index) atomic argmax per src
__global__ void k_ckey(const int* __restrict__ ei) {
    int j = blockIdx.x * blockDim.x + threadIdx.x;
    if (j >= EE) return;
    int s = ei[j], d = ei[EE + j];
    const float scale = 1.0f / sqrtf(128.0f);
    float t = ((g_p12 * g_xf[s]) * g_xf[d]) * scale;   // match reference mul order
    float sc = tanhf(t);                                // CONST == 1.0
    unsigned long long key =
        ((unsigned long long)fenc(sc) << 32) | (unsigned long long)(0xFFFFFFFFu - (unsigned)j);
    atomicMax(&g_ckey[s], key);
}

// Resolve next[] map (empty bucket -> dst0[0], matching argmax over all -inf -> idx 0)
__global__ void k_next(const int* __restrict__ ei) {
    int i = blockIdx.x * blockDim.x + threadIdx.x;
    if (i >= NN) return;
    unsigned long long key = g_ckey[i];
    int j = key ? (int)(0xFFFFFFFFu - (unsigned)(key & 0xFFFFFFFFull)) : 0;
    g_next[i] = ei[EE + j];
}

// final = next^4096(start) via 12 rounds of pointer doubling in shared memory
__global__ void k_walk(float* __restrict__ out, int out_size) {
    __shared__ int A[NN];
    __shared__ int B[NN];
    int tid = threadIdx.x;
#pragma unroll
    for (int r = 0; r < 4; r++) A[tid + r * 1024] = g_next[tid + r * 1024];
    __syncthreads();
    for (int it = 0; it < 12; it++) {
#pragma unroll
        for (int r = 0; r < 4; r++) { int i = tid + r * 1024; B[i] = A[A[i]]; }
        __syncthreads();
#pragma unroll
        for (int r = 0; r < 4; r++) { int i = tid + r * 1024; A[i] = B[i]; }
        __syncthreads();
    }
    if (tid == 0 && out_size > NN) out[NN] = (float)A[g_start];
}

// ---------------- launch ----------------
extern "C" void kernel_launch(void* const* d_in, const int* in_sizes, int n_in,
                              void* d_out, int out_size) {
    const float* x    = (const float*)d_in[0];
    const int*   ei   = (const int*)  d_in[1];
    const float* W1   = (const float*)d_in[2];
    const float* as1  = (const float*)d_in[3];
    const float* ad1  = (const float*)d_in[4];
    const float* b1   = (const float*)d_in[5];
    const float* W2   = (const float*)d_in[6];
    const float* as2  = (const float*)d_in[7];
    const float* ad2  = (const float*)d_in[8];
    const float* b2   = (const float*)d_in[9];
    const float* W3   = (const float*)d_in[10];
    const float* as3  = (const float*)d_in[11];
    const float* ad3  = (const float*)d_in[12];
    const float* b3   = (const float*)d_in[13];
    const float* phi1 = (const float*)d_in[14];
    const float* phi2 = (const float*)d_in[15];
    float* out = (float*)d_out;

    const int NB_N = (NN + 255) / 256;      // 16
    const int NB_E = (ETOT + 255) / 256;    // 528
    const int NB_C = (EE + 255) / 256;      // 512

    // Layer 1
    k_node0<<<NB_N, 256>>>(x, W1, as1, ad1);
    k_edge_max<<<NB_E, 256>>>(ei);
    k_edge_acc3<<<NB_E, 256>>>(ei);
    // Layer 2
    k_node12<<<NB_N, 256>>>(W2, as2, ad2, b1);
    k_edge_max<<<NB_E, 256>>>(ei);
    k_edge_acc3<<<NB_E, 256>>>(ei);
    // Layer 3
    k_node23<<<NB_N, 256>>>(W3, as3, ad3, b2);
    k_edge_max<<<NB_E, 256>>>(ei);
    k_edge_acc1<<<NB_E, 256>>>(ei);
    // Softmax + start + p12
    k_softmax<<<1, 1024>>>(b3, phi1, phi2, out);
    // Chain: fixed-point map + pointer doubling
    k_ckey<<<NB_C, 256>>>(ei);
    k_next<<<NB_N, 256>>>(ei);
    k_walk<<<1, 1024>>>(out, out_size);
}